// round 13
// baseline (speedup 1.0000x reference)
#include <cuda_runtime.h>
#include <math.h>
#include <stdint.h>

#define NN 100000
#define NE 600000
#define NG 256

// ---------------- scratch layout (floats) ----------------
static constexpr size_t OFF_TX    = 0;                         // [NN,640] fwd-chain Cheb slices
static constexpr size_t OFF_H1    = OFF_TX + (size_t)NN*640;   // [NN,128]
static constexpr size_t OFF_H2    = OFF_H1 + (size_t)NN*128;   // [NN,512]
static constexpr size_t OFF_DEGA  = OFF_H2 + (size_t)NN*512;
static constexpr size_t OFF_DEGB  = OFF_DEGA + NN;
static constexpr size_t OFF_DINVA = OFF_DEGB + NN;
static constexpr size_t OFF_DINVB = OFF_DINVA + NN;
static constexpr size_t OFF_POOL  = OFF_DINVB + NN;            // [NG,512]
static constexpr size_t OFF_CNT   = OFF_POOL + (size_t)NG*512; // [NG]
static constexpr size_t WT_SZ     = (size_t)256*320;           // u32 region per conv
static constexpr size_t OFF_WT    = OFF_CNT + NG;              // region 0 (fwd)
static constexpr size_t OFF_WT2   = OFF_WT + WT_SZ;            // region 1 (rev)
static constexpr size_t BUF_TOTAL = OFF_WT2 + WT_SZ;

__device__ float g_buf[BUF_TOTAL];
__device__ float g_tx2[(size_t)NN*640];    // rev-chain Cheb slices

// packed edge records: {gather_idx, weight_bits}; fwd at [0,NE), rev at [NE,2NE)
__device__ int2 g_ev[2 * NE];

// ---------------- int scratch ----------------
static constexpr int IB_ROWF = 0;
static constexpr int IB_ROWR = NN;
static constexpr int IB_CURF = 2*NN;   // after scatter: row end
static constexpr int IB_CURR = 3*NN;
static constexpr int IB_BSF  = 4*NN;
static constexpr int IB_BSR  = IB_BSF + 128;
static constexpr int IB_TOTAL= IB_BSR + 128;

__device__ int g_ib[IB_TOTAL];

static constexpr int NB = (NN + 1023) / 1024;

// ============================================================
// helpers
// ============================================================
__device__ __forceinline__ uint32_t pack_bf16(float lo, float hi) {
    uint32_t u;
    asm("cvt.rn.bf16x2.f32 %0, %1, %2;" : "=r"(u) : "f"(hi), "f"(lo));
    return u;
}

__device__ __forceinline__ void mma16816(float* d, const uint32_t* a, const uint32_t* b) {
    asm volatile(
        "mma.sync.aligned.m16n8k16.row.col.f32.bf16.bf16.f32 "
        "{%0,%1,%2,%3}, {%4,%5,%6,%7}, {%8,%9}, {%0,%1,%2,%3};"
        : "+f"(d[0]), "+f"(d[1]), "+f"(d[2]), "+f"(d[3])
        : "r"(a[0]), "r"(a[1]), "r"(a[2]), "r"(a[3]), "r"(b[0]), "r"(b[1]));
}

// ============================================================
// small utility kernels
// ============================================================
__global__ void k_zero(size_t off, int n) {
    int i = blockIdx.x * blockDim.x + threadIdx.x;
    if (i < n) g_buf[off + i] = 0.0f;
}

__global__ void k_deg(const int* __restrict__ src, const int* __restrict__ dst) {
    int e = blockIdx.x * blockDim.x + threadIdx.x;
    if (e >= NE) return;
    atomicAdd(&g_buf[OFF_DEGA + src[e]], 1.0f);
    atomicAdd(&g_buf[OFF_DEGB + dst[e]], 1.0f);
}

__global__ void k_dinv() {
    int n = blockIdx.x * blockDim.x + threadIdx.x;
    if (n >= NN) return;
    float a = g_buf[OFF_DEGA + n];
    float b = g_buf[OFF_DEGB + n];
    g_buf[OFF_DINVA + n] = (a > 0.0f) ? rsqrtf(a) : 0.0f;
    g_buf[OFF_DINVB + n] = (b > 0.0f) ? rsqrtf(b) : 0.0f;
}

// ============================================================
// CSR build: block sums -> scan -> row starts -> scatter
// ============================================================
__global__ void k_blocksum() {
    int tid  = threadIdx.x;
    int i    = blockIdx.x * 1024 + tid;
    int lane = tid & 31, wid = tid >> 5;
    int dF = (i < NN) ? (int)g_buf[OFF_DEGB + i] : 0;
    int dR = (i < NN) ? (int)g_buf[OFF_DEGA + i] : 0;
    #pragma unroll
    for (int o = 16; o > 0; o >>= 1) {
        dF += __shfl_down_sync(0xffffffffu, dF, o);
        dR += __shfl_down_sync(0xffffffffu, dR, o);
    }
    __shared__ int sF[32], sR[32];
    if (lane == 0) { sF[wid] = dF; sR[wid] = dR; }
    __syncthreads();
    if (wid == 0) {
        int vF = sF[lane], vR = sR[lane];
        #pragma unroll
        for (int o = 16; o > 0; o >>= 1) {
            vF += __shfl_down_sync(0xffffffffu, vF, o);
            vR += __shfl_down_sync(0xffffffffu, vR, o);
        }
        if (lane == 0) { g_ib[IB_BSF + blockIdx.x] = vF; g_ib[IB_BSR + blockIdx.x] = vR; }
    }
}

__global__ void k_scanblocks() {
    __shared__ int sF[128], sR[128];
    int tid = threadIdx.x;
    int vF = (tid < NB) ? g_ib[IB_BSF + tid] : 0;
    int vR = (tid < NB) ? g_ib[IB_BSR + tid] : 0;
    sF[tid] = vF; sR[tid] = vR;
    __syncthreads();
    for (int s = 1; s < 128; s <<= 1) {
        int aF = (tid >= s) ? sF[tid - s] : 0;
        int aR = (tid >= s) ? sR[tid - s] : 0;
        __syncthreads();
        sF[tid] += aF; sR[tid] += aR;
        __syncthreads();
    }
    if (tid < NB) {
        g_ib[IB_BSF + tid] = sF[tid] - vF;
        g_ib[IB_BSR + tid] = sR[tid] - vR;
    }
}

__global__ void k_writerow() {
    int tid = threadIdx.x;
    int i   = blockIdx.x * 1024 + tid;
    int lane = tid & 31, wid = tid >> 5;
    int dF = (i < NN) ? (int)g_buf[OFF_DEGB + i] : 0;
    int dR = (i < NN) ? (int)g_buf[OFF_DEGA + i] : 0;
    int iF = dF, iR = dR;
    #pragma unroll
    for (int o = 1; o < 32; o <<= 1) {
        int tF = __shfl_up_sync(0xffffffffu, iF, o);
        int tR = __shfl_up_sync(0xffffffffu, iR, o);
        if (lane >= o) { iF += tF; iR += tR; }
    }
    __shared__ int wsF[32], wsR[32];
    if (lane == 31) { wsF[wid] = iF; wsR[wid] = iR; }
    __syncthreads();
    if (wid == 0) {
        int vF = wsF[lane], vR = wsR[lane];
        int jF = vF, jR = vR;
        #pragma unroll
        for (int o = 1; o < 32; o <<= 1) {
            int tF = __shfl_up_sync(0xffffffffu, jF, o);
            int tR = __shfl_up_sync(0xffffffffu, jR, o);
            if (lane >= o) { jF += tF; jR += tR; }
        }
        wsF[lane] = jF - vF;
        wsR[lane] = jR - vR;
    }
    __syncthreads();
    int exF = (iF - dF) + wsF[wid] + g_ib[IB_BSF + blockIdx.x];
    int exR = (iR - dR) + wsR[wid] + g_ib[IB_BSR + blockIdx.x];
    if (i < NN) {
        g_ib[IB_ROWF + i] = exF; g_ib[IB_CURF + i] = exF;
        g_ib[IB_ROWR + i] = exR; g_ib[IB_CURR + i] = exR;
    }
}

__global__ void k_scatter(const int* __restrict__ src, const int* __restrict__ dst) {
    int e = blockIdx.x * blockDim.x + threadIdx.x;
    if (e >= NE) return;
    int s = src[e], d = dst[e];
    float dAs = g_buf[OFF_DINVA + s], dAd = g_buf[OFF_DINVA + d];
    float dBs = g_buf[OFF_DINVB + s], dBd = g_buf[OFF_DINVB + d];
    float wf = -dAs * dAd;
    float wr = -dBd * dBs;
    int pF = atomicAdd(&g_ib[IB_CURF + d], 1);
    g_ev[pF] = make_int2(s, __float_as_int(wf));
    int pR = atomicAdd(&g_ib[IB_CURR + s], 1);
    g_ev[NE + pR] = make_int2(d, __float_as_int(wr));
}

// ============================================================
// dual-chain Tx0 copy: same source into both chains' slice 0
// ============================================================
template<int F>
__global__ void col_copy_dual(int mode, const float* __restrict__ ext,
                              size_t srcOff, int srcLd) {
    constexpr int P = F / 4;
    constexpr int LD = 5 * F;
    int t = blockIdx.x * blockDim.x + threadIdx.x;
    if (t >= 2 * NN * P) return;
    int chain = (t >= NN * P) ? 1 : 0;
    int u = t - chain * NN * P;
    int n = u / P;
    int j = (u % P) * 4;
    float4 v;
    if (mode == 1) v = *(const float4*)(ext + (size_t)n * srcLd + j);
    else           v = *(const float4*)&g_buf[srcOff + (size_t)n * srcLd + j];
    float* cbuf = chain ? g_tx2 : g_buf;
    *(float4*)&cbuf[(size_t)n * LD + j] = v;
}

// ============================================================
// dual-chain SpMM, F=128: one warp per (chain, node); serial edge loop
// (R8-proven). First NN warps = fwd chain (g_buf TX), next NN = rev (g_tx2).
// useCommon=1: gather from g_buf[cOff] (H1); else from own chain buffer.
// ============================================================
__global__ void spmm_dual128(int useCommon, size_t cOff, int cLd,
                             size_t inOff, size_t outOff, size_t prevOff, int hasPrev) {
    int gt = blockIdx.x * 256 + threadIdx.x;
    int node = gt >> 5;
    if (node >= 2 * NN) return;
    int lane = gt & 31;
    int chain = (node >= NN) ? 1 : 0;
    int n = node - chain * NN;
    float* cbuf = chain ? g_tx2 : g_buf;
    const int2* evp = g_ev + (chain ? NE : 0);
    int start = g_ib[(chain ? IB_ROWR : IB_ROWF) + n];
    int end   = g_ib[(chain ? IB_CURR : IB_CURF) + n];
    const float* inB = (useCommon ? (g_buf + cOff) : (cbuf + inOff)) + lane * 4;
    int ld = useCommon ? cLd : 640;
    float ax = 0.f, ay = 0.f, az = 0.f, aw = 0.f;
    for (int e = start; e < end; e++) {
        int2  ev = evp[e];
        float w  = __int_as_float(ev.y);
        const float4 v = __ldg((const float4*)(inB + (size_t)ev.x * ld));
        ax = fmaf(w, v.x, ax);
        ay = fmaf(w, v.y, ay);
        az = fmaf(w, v.z, az);
        aw = fmaf(w, v.w, aw);
    }
    float4 r;
    if (hasPrev) {
        const float4 p = __ldcs((const float4*)&cbuf[prevOff + (size_t)n * 640 + lane * 4]);
        r.x = 2.f * ax - p.x; r.y = 2.f * ay - p.y;
        r.z = 2.f * az - p.z; r.w = 2.f * aw - p.w;
    } else {
        r.x = ax; r.y = ay; r.z = az; r.w = aw;
    }
    *(float4*)&cbuf[outOff + (size_t)n * 640 + lane * 4] = r;
}

// ============================================================
// dual-chain SpMM, F=16: one warp per (chain, node); EDGE-PARALLEL.
// lane = edge_slot(0..7) * 4 + quad(0..3): 8 edges gather simultaneously,
// then 3-step shfl reduction over edge slots. ext != nullptr: gather from
// external x; else from own chain buffer at inOff (ld 80).
// ============================================================
__global__ void spmm_dual16(const float* __restrict__ ext, int extLd,
                            size_t inOff, size_t outOff, size_t prevOff, int hasPrev) {
    int gt = blockIdx.x * 256 + threadIdx.x;
    int node = gt >> 5;
    if (node >= 2 * NN) return;
    int lane = gt & 31;
    int es = lane >> 2, q = lane & 3;
    int chain = (node >= NN) ? 1 : 0;
    int n = node - chain * NN;
    float* cbuf = chain ? g_tx2 : g_buf;
    const int2* evp = g_ev + (chain ? NE : 0);
    int start = g_ib[(chain ? IB_ROWR : IB_ROWF) + n];
    int end   = g_ib[(chain ? IB_CURR : IB_CURF) + n];
    const float* base = ext ? ext : (cbuf + inOff);
    int ld = ext ? extLd : 80;
    float4 a = make_float4(0.f, 0.f, 0.f, 0.f);
    for (int e = start + es; e < end; e += 8) {
        int2  ev = evp[e];
        float w  = __int_as_float(ev.y);
        const float4 v = __ldg((const float4*)(base + (size_t)ev.x * ld + q * 4));
        a.x = fmaf(w, v.x, a.x);
        a.y = fmaf(w, v.y, a.y);
        a.z = fmaf(w, v.z, a.z);
        a.w = fmaf(w, v.w, a.w);
    }
    #pragma unroll
    for (int o = 16; o >= 4; o >>= 1) {
        a.x += __shfl_down_sync(0xffffffffu, a.x, o);
        a.y += __shfl_down_sync(0xffffffffu, a.y, o);
        a.z += __shfl_down_sync(0xffffffffu, a.z, o);
        a.w += __shfl_down_sync(0xffffffffu, a.w, o);
    }
    if (lane < 4) {   // lane == quad index here
        float4 r;
        if (hasPrev) {
            const float4 p = __ldcs((const float4*)&cbuf[prevOff + (size_t)n * 80 + lane * 4]);
            r.x = 2.f * a.x - p.x; r.y = 2.f * a.y - p.y;
            r.z = 2.f * a.z - p.z; r.w = 2.f * a.w - p.w;
        } else {
            r = a;
        }
        *(float4*)&cbuf[outOff + (size_t)n * 80 + lane * 4] = r;
    }
}

// ============================================================
// weight transpose + bf16x2 pack into region wtOff
// ============================================================
__global__ void k_transb(const float* __restrict__ W, int Kdim, int FOUT, size_t wtOff) {
    int K2 = Kdim / 2;
    int t = blockIdx.x * blockDim.x + threadIdx.x;
    if (t >= FOUT * K2) return;
    int n = t / K2, k2 = t % K2;
    float lo = W[(size_t)(2 * k2) * FOUT + n];
    float hi = W[(size_t)(2 * k2 + 1) * FOUT + n];
    g_buf[wtOff + t] = __uint_as_float(pack_bf16(lo, hi));
}

// ============================================================
// bf16 mma.sync GEMM: C[:, hc0+n0 : +BN] = relu(A[NN,Kdim] @ WT^T + bias)
// A from chain buffer (aBuf: 0=g_buf, 1=g_tx2), WT from g_buf[wtOff].
// ============================================================
template<int BN, int BK>
__global__ void __launch_bounds__(256)
gemm_bf16(int aBuf, int lda, int Kdim, size_t wtOff,
          const float* __restrict__ bias, size_t cOff, int ldc, int hc0) {
    constexpr int BM = 128;
    constexpr int PW = BK / 2 + 4;
    constexpr int KS = BK / 16;
    constexpr int NT = BN / 32;
    constexpr int ASZ = BM * PW;
    constexpr int BSZ = BN * PW;
    constexpr int AOCT = BM * BK / 8;
    constexpr int AO_PER = (AOCT + 255) / 256;
    constexpr int BQ  = BN * BK / 8;
    constexpr int BO_PER = (BQ + 255) / 256;
    constexpr int OPR = BK / 8;

    __shared__ uint32_t sm[2 * ASZ + 2 * BSZ];
    uint32_t* As[2] = { sm, sm + ASZ };
    uint32_t* Bs[2] = { sm + 2 * ASZ, sm + 2 * ASZ + BSZ };

    int tid  = threadIdx.x;
    int wid  = tid >> 5;
    int lane = tid & 31;
    int wm   = wid >> 2;
    int wn   = wid & 3;
    int m0   = blockIdx.x * BM;
    int n0   = blockIdx.y * BN;
    int l4   = lane >> 2;
    int lq   = lane & 3;
    const int K2 = Kdim / 2;
    const uint32_t* WTu = (const uint32_t*)&g_buf[wtOff];
    const float* Ag = (aBuf ? g_tx2 : g_buf);

    float acc[4][NT][4];
    #pragma unroll
    for (int mt = 0; mt < 4; mt++)
        #pragma unroll
        for (int nt = 0; nt < NT; nt++)
            #pragma unroll
            for (int q = 0; q < 4; q++) acc[mt][nt][q] = 0.f;

    const int NC = Kdim / BK;

    float4 ra[AO_PER][2];
    uint4  rb[BO_PER];

    auto ldg = [&](int kc) {
        int k0 = kc * BK;
        #pragma unroll
        for (int i = 0; i < AO_PER; i++) {
            int id = tid + i * 256;
            int r = id / OPR, o = id % OPR;
            int gr = m0 + r;
            if (gr < NN) {
                ra[i][0] = *(const float4*)&Ag[(size_t)gr * lda + k0 + o * 8];
                ra[i][1] = *(const float4*)&Ag[(size_t)gr * lda + k0 + o * 8 + 4];
            } else {
                ra[i][0] = make_float4(0.f, 0.f, 0.f, 0.f);
                ra[i][1] = make_float4(0.f, 0.f, 0.f, 0.f);
            }
        }
        #pragma unroll
        for (int i = 0; i < BO_PER; i++) {
            int id = tid + i * 256;
            if ((BQ & 255) == 0 || id < BQ) {
                int r = id / OPR, q = id % OPR;
                rb[i] = *(const uint4*)&WTu[(size_t)(n0 + r) * K2 + kc * (BK / 2) + q * 4];
            }
        }
    };

    auto sts = [&](int st) {
        #pragma unroll
        for (int i = 0; i < AO_PER; i++) {
            int id = tid + i * 256;
            int r = id / OPR, o = id % OPR;
            uint4 u;
            u.x = pack_bf16(ra[i][0].x, ra[i][0].y);
            u.y = pack_bf16(ra[i][0].z, ra[i][0].w);
            u.z = pack_bf16(ra[i][1].x, ra[i][1].y);
            u.w = pack_bf16(ra[i][1].z, ra[i][1].w);
            *(uint4*)&As[st][r * PW + o * 4] = u;
        }
        #pragma unroll
        for (int i = 0; i < BO_PER; i++) {
            int id = tid + i * 256;
            if ((BQ & 255) == 0 || id < BQ) {
                int r = id / OPR, q = id % OPR;
                *(uint4*)&Bs[st][r * PW + q * 4] = rb[i];
            }
        }
    };

    auto compute = [&](int st) {
        const uint32_t* aB = As[st] + (wm * 64 + l4) * PW + lq;
        const uint32_t* bB = Bs[st] + (wn * (BN / 4) + l4) * PW + lq;
        #pragma unroll
        for (int ks = 0; ks < KS; ks++) {
            uint32_t af[4][4];
            #pragma unroll
            for (int mt = 0; mt < 4; mt++) {
                const uint32_t* p = aB + mt * 16 * PW + ks * 8;
                af[mt][0] = p[0];
                af[mt][1] = p[8 * PW];
                af[mt][2] = p[4];
                af[mt][3] = p[8 * PW + 4];
            }
            uint32_t bf[NT][2];
            #pragma unroll
            for (int nt = 0; nt < NT; nt++) {
                const uint32_t* q = bB + nt * 8 * PW + ks * 8;
                bf[nt][0] = q[0];
                bf[nt][1] = q[4];
            }
            #pragma unroll
            for (int mt = 0; mt < 4; mt++)
                #pragma unroll
                for (int nt = 0; nt < NT; nt++)
                    mma16816(acc[mt][nt], af[mt], bf[nt]);
        }
    };

    ldg(0);
    sts(0);
    __syncthreads();

    for (int c = 0; c < NC; c++) {
        int st = c & 1;
        bool has = (c + 1 < NC);
        if (has) ldg(c + 1);
        compute(st);
        if (has) sts(st ^ 1);
        __syncthreads();
    }

    #pragma unroll
    for (int mt = 0; mt < 4; mt++) {
        int row = m0 + wm * 64 + mt * 16 + l4;
        #pragma unroll
        for (int nt = 0; nt < NT; nt++) {
            int col = n0 + wn * (BN / 4) + nt * 8 + 2 * lq;
            float b0 = bias[col], b1 = bias[col + 1];
            if (row < NN) {
                float2 o0;
                o0.x = fmaxf(acc[mt][nt][0] + b0, 0.f);
                o0.y = fmaxf(acc[mt][nt][1] + b1, 0.f);
                *(float2*)&g_buf[cOff + (size_t)row * ldc + hc0 + col] = o0;
            }
            if (row + 8 < NN) {
                float2 o1;
                o1.x = fmaxf(acc[mt][nt][2] + b0, 0.f);
                o1.y = fmaxf(acc[mt][nt][3] + b1, 0.f);
                *(float2*)&g_buf[cOff + (size_t)(row + 8) * ldc + hc0 + col] = o1;
            }
        }
    }
}

// ============================================================
// pooling + head
// ============================================================
__global__ void k_cnt(const int* __restrict__ batch) {
    int i = blockIdx.x * blockDim.x + threadIdx.x;
    if (i >= NN) return;
    atomicAdd(&g_buf[OFF_CNT + batch[i]], 1.0f);
}

__global__ void pool_kernel(const int* __restrict__ batch) {
    constexpr int NPB = 512;
    __shared__ int sb[NPB];
    int n0  = blockIdx.x * NPB;
    int tid = threadIdx.x;
    int nmax = NN - n0; if (nmax > NPB) nmax = NPB;
    if (tid < nmax) sb[tid] = batch[n0 + tid];
    __syncthreads();
    int f = tid;
    float acc = 0.f;
    int cur = sb[0];
    for (int i = 0; i < nmax; i++) {
        int b = sb[i];
        if (b != cur) {
            atomicAdd(&g_buf[OFF_POOL + (size_t)cur * 512 + f], acc);
            acc = 0.f; cur = b;
        }
        acc += g_buf[OFF_H2 + (size_t)(n0 + i) * 512 + f];
    }
    atomicAdd(&g_buf[OFF_POOL + (size_t)cur * 512 + f], acc);
}

__global__ void head_kernel(const float* __restrict__ fcw, const float* __restrict__ fcb,
                            float* __restrict__ out) {
    int g = blockIdx.x;
    int tid = threadIdx.x;
    __shared__ float red[128][4];
    float acc[4] = {0.f, 0.f, 0.f, 0.f};
    for (int j = tid; j < 512; j += 128) {
        float p = g_buf[OFF_POOL + (size_t)g * 512 + j];
        #pragma unroll
        for (int c = 0; c < 4; c++) acc[c] = fmaf(p, fcw[j * 4 + c], acc[c]);
    }
    #pragma unroll
    for (int c = 0; c < 4; c++) red[tid][c] = acc[c];
    __syncthreads();
    for (int s = 64; s > 0; s >>= 1) {
        if (tid < s) {
            #pragma unroll
            for (int c = 0; c < 4; c++) red[tid][c] += red[tid + s][c];
        }
        __syncthreads();
    }
    if (tid == 0) {
        float ic = 1.0f / fmaxf(g_buf[OFF_CNT + g], 1.0f);
        float l[4];
        #pragma unroll
        for (int c = 0; c < 4; c++) l[c] = red[0][c] * ic + fcb[c];
        float m = fmaxf(fmaxf(l[0], l[1]), fmaxf(l[2], l[3]));
        float s = 0.f;
        #pragma unroll
        for (int c = 0; c < 4; c++) s += expf(l[c] - m);
        float ls = logf(s);
        #pragma unroll
        for (int c = 0; c < 4; c++) out[g * 4 + c] = l[c] - m - ls;
    }
}

// ============================================================
// host side
// ============================================================
static inline int cdiv_ll(long long a, int b) { return (int)((a + b - 1) / b); }

extern "C" void kernel_launch(void* const* d_in, const int* in_sizes, int n_in,
                              void* d_out, int out_size) {
    const float* x     = (const float*)d_in[0];
    const int*   ei    = (const int*)d_in[1];
    const int*   batch = (const int*)d_in[2];
    const float* W11   = (const float*)d_in[3];
    const float* b11   = (const float*)d_in[4];
    const float* W12   = (const float*)d_in[5];
    const float* b12   = (const float*)d_in[6];
    const float* W21   = (const float*)d_in[7];
    const float* b21   = (const float*)d_in[8];
    const float* W22   = (const float*)d_in[9];
    const float* b22   = (const float*)d_in[10];
    const float* fcw   = (const float*)d_in[11];
    const float* fcb   = (const float*)d_in[12];
    float* out = (float*)d_out;

    const int* src = ei;
    const int* dst = ei + NE;

    k_zero<<<cdiv_ll(2 * NN, 256), 256>>>(OFF_DEGA, 2 * NN);
    k_zero<<<cdiv_ll(NG * 512 + NG, 256), 256>>>(OFF_POOL, NG * 512 + NG);

    k_deg<<<cdiv_ll(NE, 256), 256>>>(src, dst);
    k_dinv<<<cdiv_ll(NN, 256), 256>>>();

    k_blocksum<<<NB, 1024>>>();
    k_scanblocks<<<1, 128>>>();
    k_writerow<<<NB, 1024>>>();
    k_scatter<<<cdiv_ll(NE, 256), 256>>>(src, dst);

    const int gWarp = cdiv_ll((long long)2 * NN * 32, 256);   // warp-per-node dual grids

    // ---- layer 1 (F=16): dual-chain, edge-parallel SpMM ----
    col_copy_dual<16><<<cdiv_ll((long long)2 * NN * 4, 256), 256>>>(1, x, 0, 16);
    spmm_dual16<<<gWarp, 256>>>(x, 16, 0, 16, 0, 0);            // T1 from x
    spmm_dual16<<<gWarp, 256>>>(nullptr, 0, 16, 32, 0, 1);      // T2
    spmm_dual16<<<gWarp, 256>>>(nullptr, 0, 32, 48, 16, 1);     // T3
    spmm_dual16<<<gWarp, 256>>>(nullptr, 0, 48, 64, 32, 1);     // T4
    k_transb<<<cdiv_ll(64 * 40, 256), 256>>>(W11, 80, 64, OFF_WT);
    {
        dim3 grid((NN + 127) / 128, 1);
        gemm_bf16<64, 16><<<grid, 256>>>(0, 80, 80, OFF_WT, b11, OFF_H1, 128, 0);
    }
    k_transb<<<cdiv_ll(64 * 40, 256), 256>>>(W12, 80, 64, OFF_WT2);
    {
        dim3 grid((NN + 127) / 128, 1);
        gemm_bf16<64, 16><<<grid, 256>>>(1, 80, 80, OFF_WT2, b12, OFF_H1, 128, 64);
    }

    // ---- layer 2 (F=128): dual-chain, warp-per-node serial-edge SpMM ----
    col_copy_dual<128><<<gWarp, 256>>>(0, nullptr, OFF_H1, 128);
    spmm_dual128<<<gWarp, 256>>>(1, OFF_H1, 128, 0, 128, 0, 0);   // T1 from H1
    spmm_dual128<<<gWarp, 256>>>(0, 0, 0, 128, 256, 0, 1);        // T2
    spmm_dual128<<<gWarp, 256>>>(0, 0, 0, 256, 384, 128, 1);      // T3
    spmm_dual128<<<gWarp, 256>>>(0, 0, 0, 384, 512, 256, 1);      // T4
    k_transb<<<cdiv_ll(256 * 320, 256), 256>>>(W21, 640, 256, OFF_WT);
    {
        dim3 grid((NN + 127) / 128, 2);
        gemm_bf16<128, 32><<<grid, 256>>>(0, 640, 640, OFF_WT, b21, OFF_H2, 512, 0);
    }
    k_transb<<<cdiv_ll(256 * 320, 256), 256>>>(W22, 640, 256, OFF_WT2);
    {
        dim3 grid((NN + 127) / 128, 2);
        gemm_bf16<128, 32><<<grid, 256>>>(1, 640, 640, OFF_WT2, b22, OFF_H2, 512, 256);
    }

    k_cnt<<<cdiv_ll(NN, 256), 256>>>(batch);
    pool_kernel<<<(NN + 511) / 512, 512>>>(batch);
    head_kernel<<<NG, 128>>>(fcw, fcb, out);
}

// round 16
// speedup vs baseline: 1.1361x; 1.1361x over previous
#include <cuda_runtime.h>
#include <math.h>
#include <stdint.h>

#define NN 100000
#define NE 600000
#define NG 256

// ---------------- scratch layout (floats) ----------------
static constexpr size_t OFF_TX    = 0;                         // [NN,640] Chebyshev slices
static constexpr size_t OFF_H1    = OFF_TX + (size_t)NN*640;   // [NN,128]
static constexpr size_t OFF_H2    = OFF_H1 + (size_t)NN*128;   // [NN,512]
static constexpr size_t OFF_DEGA  = OFF_H2 + (size_t)NN*512;   // deg over src
static constexpr size_t OFF_DEGB  = OFF_DEGA + NN;             // deg over dst
static constexpr size_t OFF_DINVA = OFF_DEGB + NN;
static constexpr size_t OFF_DINVB = OFF_DINVA + NN;
static constexpr size_t OFF_POOL  = OFF_DINVB + NN;            // [NG,512]
static constexpr size_t OFF_CNT   = OFF_POOL + (size_t)NG*512; // [NG]
static constexpr size_t OFF_WT    = OFF_CNT + NG;              // bf16x2-packed weights [256*320 u32]
static constexpr size_t BUF_TOTAL = OFF_WT + (size_t)256*320;

__device__ float g_buf[BUF_TOTAL];

// packed edge records: {gather_idx, weight_bits}; fwd at [0,NE), rev at [NE,2NE)
__device__ int2 g_ev[2 * NE];

// ---------------- int scratch ----------------
static constexpr int IB_ROWF = 0;
static constexpr int IB_ROWR = NN;
static constexpr int IB_CURF = 2*NN;   // after scatter: row end
static constexpr int IB_CURR = 3*NN;
static constexpr int IB_BSF  = 4*NN;
static constexpr int IB_BSR  = IB_BSF + 128;
static constexpr int IB_TOTAL= IB_BSR + 128;

__device__ int g_ib[IB_TOTAL];

static constexpr int NB = (NN + 1023) / 1024;

// ============================================================
// helpers
// ============================================================
__device__ __forceinline__ uint32_t pack_bf16(float lo, float hi) {
    uint32_t u;
    asm("cvt.rn.bf16x2.f32 %0, %1, %2;" : "=r"(u) : "f"(hi), "f"(lo));
    return u;
}

__device__ __forceinline__ void mma16816(float* d, const uint32_t* a, const uint32_t* b) {
    asm volatile(
        "mma.sync.aligned.m16n8k16.row.col.f32.bf16.bf16.f32 "
        "{%0,%1,%2,%3}, {%4,%5,%6,%7}, {%8,%9}, {%0,%1,%2,%3};"
        : "+f"(d[0]), "+f"(d[1]), "+f"(d[2]), "+f"(d[3])
        : "r"(a[0]), "r"(a[1]), "r"(a[2]), "r"(a[3]), "r"(b[0]), "r"(b[1]));
}

// ============================================================
// small utility kernels
// ============================================================
__global__ void k_zero(size_t off, int n) {
    int i = blockIdx.x * blockDim.x + threadIdx.x;
    if (i < n) g_buf[off + i] = 0.0f;
}

__global__ void k_deg(const int* __restrict__ src, const int* __restrict__ dst) {
    int e = blockIdx.x * blockDim.x + threadIdx.x;
    if (e >= NE) return;
    atomicAdd(&g_buf[OFF_DEGA + src[e]], 1.0f);
    atomicAdd(&g_buf[OFF_DEGB + dst[e]], 1.0f);
}

__global__ void k_dinv() {
    int n = blockIdx.x * blockDim.x + threadIdx.x;
    if (n >= NN) return;
    float a = g_buf[OFF_DEGA + n];
    float b = g_buf[OFF_DEGB + n];
    g_buf[OFF_DINVA + n] = (a > 0.0f) ? rsqrtf(a) : 0.0f;
    g_buf[OFF_DINVB + n] = (b > 0.0f) ? rsqrtf(b) : 0.0f;
}

// ============================================================
// CSR build: block sums -> scan -> row starts -> scatter
// ============================================================
__global__ void k_blocksum() {
    int tid  = threadIdx.x;
    int i    = blockIdx.x * 1024 + tid;
    int lane = tid & 31, wid = tid >> 5;
    int dF = (i < NN) ? (int)g_buf[OFF_DEGB + i] : 0;
    int dR = (i < NN) ? (int)g_buf[OFF_DEGA + i] : 0;
    #pragma unroll
    for (int o = 16; o > 0; o >>= 1) {
        dF += __shfl_down_sync(0xffffffffu, dF, o);
        dR += __shfl_down_sync(0xffffffffu, dR, o);
    }
    __shared__ int sF[32], sR[32];
    if (lane == 0) { sF[wid] = dF; sR[wid] = dR; }
    __syncthreads();
    if (wid == 0) {
        int vF = sF[lane], vR = sR[lane];
        #pragma unroll
        for (int o = 16; o > 0; o >>= 1) {
            vF += __shfl_down_sync(0xffffffffu, vF, o);
            vR += __shfl_down_sync(0xffffffffu, vR, o);
        }
        if (lane == 0) { g_ib[IB_BSF + blockIdx.x] = vF; g_ib[IB_BSR + blockIdx.x] = vR; }
    }
}

__global__ void k_scanblocks() {
    __shared__ int sF[128], sR[128];
    int tid = threadIdx.x;
    int vF = (tid < NB) ? g_ib[IB_BSF + tid] : 0;
    int vR = (tid < NB) ? g_ib[IB_BSR + tid] : 0;
    sF[tid] = vF; sR[tid] = vR;
    __syncthreads();
    for (int s = 1; s < 128; s <<= 1) {
        int aF = (tid >= s) ? sF[tid - s] : 0;
        int aR = (tid >= s) ? sR[tid - s] : 0;
        __syncthreads();
        sF[tid] += aF; sR[tid] += aR;
        __syncthreads();
    }
    if (tid < NB) {
        g_ib[IB_BSF + tid] = sF[tid] - vF;
        g_ib[IB_BSR + tid] = sR[tid] - vR;
    }
}

__global__ void k_writerow() {
    int tid = threadIdx.x;
    int i   = blockIdx.x * 1024 + tid;
    int lane = tid & 31, wid = tid >> 5;
    int dF = (i < NN) ? (int)g_buf[OFF_DEGB + i] : 0;
    int dR = (i < NN) ? (int)g_buf[OFF_DEGA + i] : 0;
    int iF = dF, iR = dR;
    #pragma unroll
    for (int o = 1; o < 32; o <<= 1) {
        int tF = __shfl_up_sync(0xffffffffu, iF, o);
        int tR = __shfl_up_sync(0xffffffffu, iR, o);
        if (lane >= o) { iF += tF; iR += tR; }
    }
    __shared__ int wsF[32], wsR[32];
    if (lane == 31) { wsF[wid] = iF; wsR[wid] = iR; }
    __syncthreads();
    if (wid == 0) {
        int vF = wsF[lane], vR = wsR[lane];
        int jF = vF, jR = vR;
        #pragma unroll
        for (int o = 1; o < 32; o <<= 1) {
            int tF = __shfl_up_sync(0xffffffffu, jF, o);
            int tR = __shfl_up_sync(0xffffffffu, jR, o);
            if (lane >= o) { jF += tF; jR += tR; }
        }
        wsF[lane] = jF - vF;
        wsR[lane] = jR - vR;
    }
    __syncthreads();
    int exF = (iF - dF) + wsF[wid] + g_ib[IB_BSF + blockIdx.x];
    int exR = (iR - dR) + wsR[wid] + g_ib[IB_BSR + blockIdx.x];
    if (i < NN) {
        g_ib[IB_ROWF + i] = exF; g_ib[IB_CURF + i] = exF;
        g_ib[IB_ROWR + i] = exR; g_ib[IB_CURR + i] = exR;
    }
}

__global__ void k_scatter(const int* __restrict__ src, const int* __restrict__ dst) {
    int e = blockIdx.x * blockDim.x + threadIdx.x;
    if (e >= NE) return;
    int s = src[e], d = dst[e];
    float dAs = g_buf[OFF_DINVA + s], dAd = g_buf[OFF_DINVA + d];
    float dBs = g_buf[OFF_DINVB + s], dBd = g_buf[OFF_DINVB + d];
    float wf = -dAs * dAd;
    float wr = -dBd * dBs;
    int pF = atomicAdd(&g_ib[IB_CURF + d], 1);
    g_ev[pF] = make_int2(s, __float_as_int(wf));
    int pR = atomicAdd(&g_ib[IB_CURR + s], 1);
    g_ev[NE + pR] = make_int2(d, __float_as_int(wr));
}

// ============================================================
// copy Tx0 slice into TxAll[:,0:F]
// ============================================================
template<int F>
__global__ void col_copy(size_t dstOff, int dstLd, int mode,
                         const float* __restrict__ ext, size_t srcOff, int srcLd) {
    constexpr int P = F / 4;
    int t = blockIdx.x * blockDim.x + threadIdx.x;
    if (t >= NN * P) return;
    int n = t / P;
    int j = (t % P) * 4;
    float4 v;
    if (mode == 1) v = *(const float4*)(ext + (size_t)n * srcLd + j);
    else           v = *(const float4*)&g_buf[srcOff + (size_t)n * srcLd + j];
    *(float4*)&g_buf[dstOff + (size_t)n * dstLd + j] = v;
}

// ============================================================
// layer-2 SpMM (F=128): warp per node, serial edge loop (R11-proven).
// prev read evict-first (.cs); gathers via __ldg.
// ============================================================
template<int F>
__global__ void spmm_f(size_t inOff, size_t outOff, size_t prevOff, int hasPrev,
                       int ld, int rowBase, int curBase, int evBase) {
    constexpr int LPN = F / 4;
    int gtid = blockIdx.x * blockDim.x + threadIdx.x;
    int node = gtid / LPN;
    if (node >= NN) return;
    int sub = gtid % LPN;
    int start = g_ib[rowBase + node];
    int end   = g_ib[curBase + node];
    float ax = 0.f, ay = 0.f, az = 0.f, aw = 0.f;
    const float* inB = g_buf + inOff + sub * 4;
    const int2* evp = g_ev + evBase;
    for (int e = start; e < end; e++) {
        int2  ev = evp[e];
        float w  = __int_as_float(ev.y);
        const float4 v = __ldg((const float4*)(inB + (size_t)ev.x * ld));
        ax = fmaf(w, v.x, ax);
        ay = fmaf(w, v.y, ay);
        az = fmaf(w, v.z, az);
        aw = fmaf(w, v.w, aw);
    }
    float4 r;
    if (hasPrev) {
        const float4 p = __ldcs((const float4*)&g_buf[prevOff + (size_t)node * ld + sub * 4]);
        r.x = 2.f * ax - p.x; r.y = 2.f * ay - p.y;
        r.z = 2.f * az - p.z; r.w = 2.f * aw - p.w;
    } else {
        r.x = ax; r.y = ay; r.z = az; r.w = aw;
    }
    *(float4*)&g_buf[outOff + (size_t)node * ld + sub * 4] = r;
}

// ============================================================
// layer-1 SpMM (F=16): warp per node, EDGE-PARALLEL.
// lane = edge_slot(0..7)*4 + quad(0..3): 8 edges gather simultaneously,
// then 3-step shfl reduction over edge slots (validated in R13).
// ext != nullptr: gather from external x (ld extLd); else from g_buf[inOff] (ld 80).
// ============================================================
__global__ void spmm16ep(const float* __restrict__ ext, int extLd,
                         size_t inOff, size_t outOff, size_t prevOff, int hasPrev,
                         int rowBase, int curBase, int evBase) {
    int gt = blockIdx.x * 256 + threadIdx.x;
    int node = gt >> 5;
    if (node >= NN) return;
    int lane = gt & 31;
    int es = lane >> 2, q = lane & 3;
    int start = g_ib[rowBase + node];
    int end   = g_ib[curBase + node];
    const float* base = ext ? ext : (g_buf + inOff);
    int ld = ext ? extLd : 80;
    const int2* evp = g_ev + evBase;
    float4 a = make_float4(0.f, 0.f, 0.f, 0.f);
    for (int e = start + es; e < end; e += 8) {
        int2  ev = evp[e];
        float w  = __int_as_float(ev.y);
        const float4 v = __ldg((const float4*)(base + (size_t)ev.x * ld + q * 4));
        a.x = fmaf(w, v.x, a.x);
        a.y = fmaf(w, v.y, a.y);
        a.z = fmaf(w, v.z, a.z);
        a.w = fmaf(w, v.w, a.w);
    }
    #pragma unroll
    for (int o = 16; o >= 4; o >>= 1) {
        a.x += __shfl_down_sync(0xffffffffu, a.x, o);
        a.y += __shfl_down_sync(0xffffffffu, a.y, o);
        a.z += __shfl_down_sync(0xffffffffu, a.z, o);
        a.w += __shfl_down_sync(0xffffffffu, a.w, o);
    }
    if (lane < 4) {   // lane == quad index
        float4 r;
        if (hasPrev) {
            const float4 p = __ldcs((const float4*)&g_buf[prevOff + (size_t)node * 80 + lane * 4]);
            r.x = 2.f * a.x - p.x; r.y = 2.f * a.y - p.y;
            r.z = 2.f * a.z - p.z; r.w = 2.f * a.w - p.w;
        } else {
            r = a;
        }
        *(float4*)&g_buf[outOff + (size_t)node * 80 + lane * 4] = r;
    }
}

// ============================================================
// weight transpose + bf16x2 pack
// ============================================================
__global__ void k_transb(const float* __restrict__ W, int Kdim, int FOUT) {
    int K2 = Kdim / 2;
    int t = blockIdx.x * blockDim.x + threadIdx.x;
    if (t >= FOUT * K2) return;
    int n = t / K2, k2 = t % K2;
    float lo = W[(size_t)(2 * k2) * FOUT + n];
    float hi = W[(size_t)(2 * k2 + 1) * FOUT + n];
    g_buf[OFF_WT + t] = __uint_as_float(pack_bf16(lo, hi));
}

// ============================================================
// bf16 mma.sync GEMM: C[:, hc0 + n0 : +BN] = relu(A[NN,Kdim] @ WT^T + bias)
// ============================================================
template<int BN, int BK>
__global__ void __launch_bounds__(256)
gemm_bf16(size_t aOff, int lda, int Kdim,
          const float* __restrict__ bias, size_t cOff, int ldc, int hc0) {
    constexpr int BM = 128;
    constexpr int PW = BK / 2 + 4;
    constexpr int KS = BK / 16;
    constexpr int NT = BN / 32;
    constexpr int ASZ = BM * PW;
    constexpr int BSZ = BN * PW;
    constexpr int AOCT = BM * BK / 8;
    constexpr int AO_PER = (AOCT + 255) / 256;
    constexpr int BQ  = BN * BK / 8;
    constexpr int BO_PER = (BQ + 255) / 256;
    constexpr int OPR = BK / 8;

    __shared__ uint32_t sm[2 * ASZ + 2 * BSZ];
    uint32_t* As[2] = { sm, sm + ASZ };
    uint32_t* Bs[2] = { sm + 2 * ASZ, sm + 2 * ASZ + BSZ };

    int tid  = threadIdx.x;
    int wid  = tid >> 5;
    int lane = tid & 31;
    int wm   = wid >> 2;
    int wn   = wid & 3;
    int m0   = blockIdx.x * BM;
    int n0   = blockIdx.y * BN;
    int l4   = lane >> 2;
    int lq   = lane & 3;
    const int K2 = Kdim / 2;
    const uint32_t* WTu = (const uint32_t*)&g_buf[OFF_WT];

    float acc[4][NT][4];
    #pragma unroll
    for (int mt = 0; mt < 4; mt++)
        #pragma unroll
        for (int nt = 0; nt < NT; nt++)
            #pragma unroll
            for (int q = 0; q < 4; q++) acc[mt][nt][q] = 0.f;

    const int NC = Kdim / BK;

    float4 ra[AO_PER][2];
    uint4  rb[BO_PER];

    auto ldg = [&](int kc) {
        int k0 = kc * BK;
        #pragma unroll
        for (int i = 0; i < AO_PER; i++) {
            int id = tid + i * 256;
            int r = id / OPR, o = id % OPR;
            int gr = m0 + r;
            if (gr < NN) {
                ra[i][0] = *(const float4*)&g_buf[aOff + (size_t)gr * lda + k0 + o * 8];
                ra[i][1] = *(const float4*)&g_buf[aOff + (size_t)gr * lda + k0 + o * 8 + 4];
            } else {
                ra[i][0] = make_float4(0.f, 0.f, 0.f, 0.f);
                ra[i][1] = make_float4(0.f, 0.f, 0.f, 0.f);
            }
        }
        #pragma unroll
        for (int i = 0; i < BO_PER; i++) {
            int id = tid + i * 256;
            if ((BQ & 255) == 0 || id < BQ) {
                int r = id / OPR, q = id % OPR;
                rb[i] = *(const uint4*)&WTu[(size_t)(n0 + r) * K2 + kc * (BK / 2) + q * 4];
            }
        }
    };

    auto sts = [&](int st) {
        #pragma unroll
        for (int i = 0; i < AO_PER; i++) {
            int id = tid + i * 256;
            int r = id / OPR, o = id % OPR;
            uint4 u;
            u.x = pack_bf16(ra[i][0].x, ra[i][0].y);
            u.y = pack_bf16(ra[i][0].z, ra[i][0].w);
            u.z = pack_bf16(ra[i][1].x, ra[i][1].y);
            u.w = pack_bf16(ra[i][1].z, ra[i][1].w);
            *(uint4*)&As[st][r * PW + o * 4] = u;
        }
        #pragma unroll
        for (int i = 0; i < BO_PER; i++) {
            int id = tid + i * 256;
            if ((BQ & 255) == 0 || id < BQ) {
                int r = id / OPR, q = id % OPR;
                *(uint4*)&Bs[st][r * PW + q * 4] = rb[i];
            }
        }
    };

    auto compute = [&](int st) {
        const uint32_t* aB = As[st] + (wm * 64 + l4) * PW + lq;
        const uint32_t* bB = Bs[st] + (wn * (BN / 4) + l4) * PW + lq;
        #pragma unroll
        for (int ks = 0; ks < KS; ks++) {
            uint32_t af[4][4];
            #pragma unroll
            for (int mt = 0; mt < 4; mt++) {
                const uint32_t* p = aB + mt * 16 * PW + ks * 8;
                af[mt][0] = p[0];
                af[mt][1] = p[8 * PW];
                af[mt][2] = p[4];
                af[mt][3] = p[8 * PW + 4];
            }
            uint32_t bf[NT][2];
            #pragma unroll
            for (int nt = 0; nt < NT; nt++) {
                const uint32_t* q = bB + nt * 8 * PW + ks * 8;
                bf[nt][0] = q[0];
                bf[nt][1] = q[4];
            }
            #pragma unroll
            for (int mt = 0; mt < 4; mt++)
                #pragma unroll
                for (int nt = 0; nt < NT; nt++)
                    mma16816(acc[mt][nt], af[mt], bf[nt]);
        }
    };

    ldg(0);
    sts(0);
    __syncthreads();

    for (int c = 0; c < NC; c++) {
        int st = c & 1;
        bool has = (c + 1 < NC);
        if (has) ldg(c + 1);
        compute(st);
        if (has) sts(st ^ 1);
        __syncthreads();
    }

    #pragma unroll
    for (int mt = 0; mt < 4; mt++) {
        int row = m0 + wm * 64 + mt * 16 + l4;
        #pragma unroll
        for (int nt = 0; nt < NT; nt++) {
            int col = n0 + wn * (BN / 4) + nt * 8 + 2 * lq;
            float b0 = bias[col], b1 = bias[col + 1];
            if (row < NN) {
                float2 o0;
                o0.x = fmaxf(acc[mt][nt][0] + b0, 0.f);
                o0.y = fmaxf(acc[mt][nt][1] + b1, 0.f);
                *(float2*)&g_buf[cOff + (size_t)row * ldc + hc0 + col] = o0;
            }
            if (row + 8 < NN) {
                float2 o1;
                o1.x = fmaxf(acc[mt][nt][2] + b0, 0.f);
                o1.y = fmaxf(acc[mt][nt][3] + b1, 0.f);
                *(float2*)&g_buf[cOff + (size_t)(row + 8) * ldc + hc0 + col] = o1;
            }
        }
    }
}

// ============================================================
// pooling + head
// ============================================================
__global__ void k_cnt(const int* __restrict__ batch) {
    int i = blockIdx.x * blockDim.x + threadIdx.x;
    if (i >= NN) return;
    atomicAdd(&g_buf[OFF_CNT + batch[i]], 1.0f);
}

__global__ void pool_kernel(const int* __restrict__ batch) {
    constexpr int NPB = 512;
    __shared__ int sb[NPB];
    int n0  = blockIdx.x * NPB;
    int tid = threadIdx.x;
    int nmax = NN - n0; if (nmax > NPB) nmax = NPB;
    if (tid < nmax) sb[tid] = batch[n0 + tid];
    __syncthreads();
    int f = tid;
    float acc = 0.f;
    int cur = sb[0];
    for (int i = 0; i < nmax; i++) {
        int b = sb[i];
        if (b != cur) {
            atomicAdd(&g_buf[OFF_POOL + (size_t)cur * 512 + f], acc);
            acc = 0.f; cur = b;
        }
        acc += g_buf[OFF_H2 + (size_t)(n0 + i) * 512 + f];
    }
    atomicAdd(&g_buf[OFF_POOL + (size_t)cur * 512 + f], acc);
}

__global__ void head_kernel(const float* __restrict__ fcw, const float* __restrict__ fcb,
                            float* __restrict__ out) {
    int g = blockIdx.x;
    int tid = threadIdx.x;
    __shared__ float red[128][4];
    float acc[4] = {0.f, 0.f, 0.f, 0.f};
    for (int j = tid; j < 512; j += 128) {
        float p = g_buf[OFF_POOL + (size_t)g * 512 + j];
        #pragma unroll
        for (int c = 0; c < 4; c++) acc[c] = fmaf(p, fcw[j * 4 + c], acc[c]);
    }
    #pragma unroll
    for (int c = 0; c < 4; c++) red[tid][c] = acc[c];
    __syncthreads();
    for (int s = 64; s > 0; s >>= 1) {
        if (tid < s) {
            #pragma unroll
            for (int c = 0; c < 4; c++) red[tid][c] += red[tid + s][c];
        }
        __syncthreads();
    }
    if (tid == 0) {
        float ic = 1.0f / fmaxf(g_buf[OFF_CNT + g], 1.0f);
        float l[4];
        #pragma unroll
        for (int c = 0; c < 4; c++) l[c] = red[0][c] * ic + fcb[c];
        float m = fmaxf(fmaxf(l[0], l[1]), fmaxf(l[2], l[3]));
        float s = 0.f;
        #pragma unroll
        for (int c = 0; c < 4; c++) s += expf(l[c] - m);
        float ls = logf(s);
        #pragma unroll
        for (int c = 0; c < 4; c++) out[g * 4 + c] = l[c] - m - ls;
    }
}

// ============================================================
// host side
// ============================================================
static inline int cdiv_ll(long long a, int b) { return (int)((a + b - 1) / b); }

// layer-1 conv (F=16): edge-parallel SpMM chain, then stacked GEMM
static void run_conv1(const float* x, int rowBase, int curBase, int evBase,
                      const float* Wstack, const float* bias, int hc0) {
    const int gWarp = cdiv_ll((long long)NN * 32, 256);
    col_copy<16><<<cdiv_ll((long long)NN * 4, 256), 256>>>(OFF_TX, 80, 1, x, 0, 16);
    spmm16ep<<<gWarp, 256>>>(x, 16, 0, 16, 0, 0, rowBase, curBase, evBase);        // T1
    spmm16ep<<<gWarp, 256>>>(nullptr, 0, 16, 32,  0, 1, rowBase, curBase, evBase); // T2
    spmm16ep<<<gWarp, 256>>>(nullptr, 0, 32, 48, 16, 1, rowBase, curBase, evBase); // T3
    spmm16ep<<<gWarp, 256>>>(nullptr, 0, 48, 64, 32, 1, rowBase, curBase, evBase); // T4
    k_transb<<<cdiv_ll(64 * 40, 256), 256>>>(Wstack, 80, 64);
    dim3 grid((NN + 127) / 128, 1);
    gemm_bf16<64, 16><<<grid, 256>>>(OFF_TX, 80, 80, bias, OFF_H1, 128, hc0);
}

// layer-2 conv (F=128): R11-proven serial-edge SpMM chain, then stacked GEMM
static void run_conv2(int rowBase, int curBase, int evBase,
                      const float* Wstack, const float* bias, int hc0) {
    constexpr int LD = 640;
    int spGrid = cdiv_ll((long long)NN * 32, 256);
    col_copy<128><<<spGrid, 256>>>(OFF_TX, LD, 2, nullptr, OFF_H1, 128);
    spmm_f<128><<<spGrid, 256>>>(OFF_TX, OFF_TX + 128, 0, 0, LD,
                                 rowBase, curBase, evBase);
    for (int k = 2; k < 5; k++) {
        spmm_f<128><<<spGrid, 256>>>(OFF_TX + (size_t)(k - 1) * 128,
                                     OFF_TX + (size_t)k * 128,
                                     OFF_TX + (size_t)(k - 2) * 128, 1, LD,
                                     rowBase, curBase, evBase);
    }
    k_transb<<<cdiv_ll(256 * 320, 256), 256>>>(Wstack, LD, 256);
    dim3 grid((NN + 127) / 128, 2);
    gemm_bf16<128, 32><<<grid, 256>>>(OFF_TX, LD, LD, bias, OFF_H2, 512, hc0);
}

extern "C" void kernel_launch(void* const* d_in, const int* in_sizes, int n_in,
                              void* d_out, int out_size) {
    const float* x     = (const float*)d_in[0];
    const int*   ei    = (const int*)d_in[1];
    const int*   batch = (const int*)d_in[2];
    const float* W11   = (const float*)d_in[3];
    const float* b11   = (const float*)d_in[4];
    const float* W12   = (const float*)d_in[5];
    const float* b12   = (const float*)d_in[6];
    const float* W21   = (const float*)d_in[7];
    const float* b21   = (const float*)d_in[8];
    const float* W22   = (const float*)d_in[9];
    const float* b22   = (const float*)d_in[10];
    const float* fcw   = (const float*)d_in[11];
    const float* fcb   = (const float*)d_in[12];
    float* out = (float*)d_out;

    const int* src = ei;
    const int* dst = ei + NE;

    k_zero<<<cdiv_ll(2 * NN, 256), 256>>>(OFF_DEGA, 2 * NN);
    k_zero<<<cdiv_ll(NG * 512 + NG, 256), 256>>>(OFF_POOL, NG * 512 + NG);

    k_deg<<<cdiv_ll(NE, 256), 256>>>(src, dst);
    k_dinv<<<cdiv_ll(NN, 256), 256>>>();

    k_blocksum<<<NB, 1024>>>();
    k_scanblocks<<<1, 128>>>();
    k_writerow<<<NB, 1024>>>();
    k_scatter<<<cdiv_ll(NE, 256), 256>>>(src, dst);

    // layer 1: fwd then rev, strictly serial (concurrency thrashes L2: R12/R13)
    run_conv1(x, IB_ROWF, IB_CURF, 0,  W11, b11, 0);
    run_conv1(x, IB_ROWR, IB_CURR, NE, W12, b12, 64);

    // layer 2: fwd then rev
    run_conv2(IB_ROWF, IB_CURF, 0,  W21, b21, 0);
    run_conv2(IB_ROWR, IB_CURR, NE, W22, b22, 256);

    k_cnt<<<cdiv_ll(NN, 256), 256>>>(batch);
    pool_kernel<<<(NN + 511) / 512, 512>>>(batch);
    head_kernel<<<NG, 128>>>(fcw, fcb, out);
}

// round 17
// speedup vs baseline: 1.2837x; 1.1299x over previous
#include <cuda_runtime.h>
#include <math.h>
#include <stdint.h>

#define NN 100000
#define NE 600000
#define NG 256

// ---------------- scratch layout (floats) ----------------
static constexpr size_t OFF_TX    = 0;                         // [NN,640] Chebyshev slices (slice0 unused)
static constexpr size_t OFF_H1    = OFF_TX + (size_t)NN*640;   // [NN,128]
static constexpr size_t OFF_H2    = OFF_H1 + (size_t)NN*128;   // [NN,512]
static constexpr size_t OFF_DEGA  = OFF_H2 + (size_t)NN*512;   // deg over src
static constexpr size_t OFF_DEGB  = OFF_DEGA + NN;             // deg over dst
static constexpr size_t OFF_DINVA = OFF_DEGB + NN;
static constexpr size_t OFF_DINVB = OFF_DINVA + NN;
static constexpr size_t OFF_POOL  = OFF_DINVB + NN;            // [NG,512]
static constexpr size_t OFF_CNT   = OFF_POOL + (size_t)NG*512; // [NG]
static constexpr size_t OFF_WT    = OFF_CNT + NG;              // bf16x2-packed weights [256*320 u32]
static constexpr size_t BUF_TOTAL = OFF_WT + (size_t)256*320;

__device__ float g_buf[BUF_TOTAL];

// packed edge records: {gather_idx, weight_bits}; fwd at [0,NE), rev at [NE,2NE)
__device__ int2 g_ev[2 * NE];

// ---------------- int scratch ----------------
static constexpr int IB_ROWF = 0;
static constexpr int IB_ROWR = NN;
static constexpr int IB_CURF = 2*NN;   // after scatter: row end
static constexpr int IB_CURR = 3*NN;
static constexpr int IB_BSF  = 4*NN;
static constexpr int IB_BSR  = IB_BSF + 128;
static constexpr int IB_TOTAL= IB_BSR + 128;

__device__ int g_ib[IB_TOTAL];

static constexpr int NB = (NN + 1023) / 1024;

// ============================================================
// helpers
// ============================================================
__device__ __forceinline__ uint32_t pack_bf16(float lo, float hi) {
    uint32_t u;
    asm("cvt.rn.bf16x2.f32 %0, %1, %2;" : "=r"(u) : "f"(hi), "f"(lo));
    return u;
}

__device__ __forceinline__ void mma16816(float* d, const uint32_t* a, const uint32_t* b) {
    asm volatile(
        "mma.sync.aligned.m16n8k16.row.col.f32.bf16.bf16.f32 "
        "{%0,%1,%2,%3}, {%4,%5,%6,%7}, {%8,%9}, {%0,%1,%2,%3};"
        : "+f"(d[0]), "+f"(d[1]), "+f"(d[2]), "+f"(d[3])
        : "r"(a[0]), "r"(a[1]), "r"(a[2]), "r"(a[3]), "r"(b[0]), "r"(b[1]));
}

// ============================================================
// small utility kernels
// ============================================================
__global__ void k_zero(size_t off, int n) {
    int i = blockIdx.x * blockDim.x + threadIdx.x;
    if (i < n) g_buf[off + i] = 0.0f;
}

__global__ void k_deg(const int* __restrict__ src, const int* __restrict__ dst) {
    int e = blockIdx.x * blockDim.x + threadIdx.x;
    if (e >= NE) return;
    atomicAdd(&g_buf[OFF_DEGA + src[e]], 1.0f);
    atomicAdd(&g_buf[OFF_DEGB + dst[e]], 1.0f);
}

__global__ void k_dinv() {
    int n = blockIdx.x * blockDim.x + threadIdx.x;
    if (n >= NN) return;
    float a = g_buf[OFF_DEGA + n];
    float b = g_buf[OFF_DEGB + n];
    g_buf[OFF_DINVA + n] = (a > 0.0f) ? rsqrtf(a) : 0.0f;
    g_buf[OFF_DINVB + n] = (b > 0.0f) ? rsqrtf(b) : 0.0f;
}

// ============================================================
// CSR build: block sums -> scan -> row starts -> scatter
// ============================================================
__global__ void k_blocksum() {
    int tid  = threadIdx.x;
    int i    = blockIdx.x * 1024 + tid;
    int lane = tid & 31, wid = tid >> 5;
    int dF = (i < NN) ? (int)g_buf[OFF_DEGB + i] : 0;
    int dR = (i < NN) ? (int)g_buf[OFF_DEGA + i] : 0;
    #pragma unroll
    for (int o = 16; o > 0; o >>= 1) {
        dF += __shfl_down_sync(0xffffffffu, dF, o);
        dR += __shfl_down_sync(0xffffffffu, dR, o);
    }
    __shared__ int sF[32], sR[32];
    if (lane == 0) { sF[wid] = dF; sR[wid] = dR; }
    __syncthreads();
    if (wid == 0) {
        int vF = sF[lane], vR = sR[lane];
        #pragma unroll
        for (int o = 16; o > 0; o >>= 1) {
            vF += __shfl_down_sync(0xffffffffu, vF, o);
            vR += __shfl_down_sync(0xffffffffu, vR, o);
        }
        if (lane == 0) { g_ib[IB_BSF + blockIdx.x] = vF; g_ib[IB_BSR + blockIdx.x] = vR; }
    }
}

__global__ void k_scanblocks() {
    __shared__ int sF[128], sR[128];
    int tid = threadIdx.x;
    int vF = (tid < NB) ? g_ib[IB_BSF + tid] : 0;
    int vR = (tid < NB) ? g_ib[IB_BSR + tid] : 0;
    sF[tid] = vF; sR[tid] = vR;
    __syncthreads();
    for (int s = 1; s < 128; s <<= 1) {
        int aF = (tid >= s) ? sF[tid - s] : 0;
        int aR = (tid >= s) ? sR[tid - s] : 0;
        __syncthreads();
        sF[tid] += aF; sR[tid] += aR;
        __syncthreads();
    }
    if (tid < NB) {
        g_ib[IB_BSF + tid] = sF[tid] - vF;
        g_ib[IB_BSR + tid] = sR[tid] - vR;
    }
}

__global__ void k_writerow() {
    int tid = threadIdx.x;
    int i   = blockIdx.x * 1024 + tid;
    int lane = tid & 31, wid = tid >> 5;
    int dF = (i < NN) ? (int)g_buf[OFF_DEGB + i] : 0;
    int dR = (i < NN) ? (int)g_buf[OFF_DEGA + i] : 0;
    int iF = dF, iR = dR;
    #pragma unroll
    for (int o = 1; o < 32; o <<= 1) {
        int tF = __shfl_up_sync(0xffffffffu, iF, o);
        int tR = __shfl_up_sync(0xffffffffu, iR, o);
        if (lane >= o) { iF += tF; iR += tR; }
    }
    __shared__ int wsF[32], wsR[32];
    if (lane == 31) { wsF[wid] = iF; wsR[wid] = iR; }
    __syncthreads();
    if (wid == 0) {
        int vF = wsF[lane], vR = wsR[lane];
        int jF = vF, jR = vR;
        #pragma unroll
        for (int o = 1; o < 32; o <<= 1) {
            int tF = __shfl_up_sync(0xffffffffu, jF, o);
            int tR = __shfl_up_sync(0xffffffffu, jR, o);
            if (lane >= o) { jF += tF; jR += tR; }
        }
        wsF[lane] = jF - vF;
        wsR[lane] = jR - vR;
    }
    __syncthreads();
    int exF = (iF - dF) + wsF[wid] + g_ib[IB_BSF + blockIdx.x];
    int exR = (iR - dR) + wsR[wid] + g_ib[IB_BSR + blockIdx.x];
    if (i < NN) {
        g_ib[IB_ROWF + i] = exF; g_ib[IB_CURF + i] = exF;
        g_ib[IB_ROWR + i] = exR; g_ib[IB_CURR + i] = exR;
    }
}

__global__ void k_scatter(const int* __restrict__ src, const int* __restrict__ dst) {
    int e = blockIdx.x * blockDim.x + threadIdx.x;
    if (e >= NE) return;
    int s = src[e], d = dst[e];
    float dAs = g_buf[OFF_DINVA + s], dAd = g_buf[OFF_DINVA + d];
    float dBs = g_buf[OFF_DINVB + s], dBd = g_buf[OFF_DINVB + d];
    float wf = -dAs * dAd;
    float wr = -dBd * dBs;
    int pF = atomicAdd(&g_ib[IB_CURF + d], 1);
    g_ev[pF] = make_int2(s, __float_as_int(wf));
    int pR = atomicAdd(&g_ib[IB_CURR + s], 1);
    g_ev[NE + pR] = make_int2(d, __float_as_int(wr));
}

// ============================================================
// SpMM: warp-packed (F/4 lanes per node), serial edge loop (R11-proven).
// Source selection: inExt -> gather from ext (ld inLd), else g_buf[inOff];
// prevExt -> prev from ext, else g_buf[prevOff]. prevStream=1 -> __ldcs
// (dead TX slices only); live buffers (H1/x) use normal loads.
// Output always into g_buf[outOff] with ld 5F.
// ============================================================
template<int F>
__global__ void spmm_f(const float* __restrict__ ext,
                       int inExt, size_t inOff, int inLd,
                       int prevExt, size_t prevOff, int prevLd, int prevStream,
                       size_t outOff, int hasPrev,
                       int rowBase, int curBase, int evBase) {
    constexpr int LPN = F / 4;
    constexpr int LD = 5 * F;
    int gtid = blockIdx.x * blockDim.x + threadIdx.x;
    int node = gtid / LPN;
    if (node >= NN) return;
    int sub = gtid % LPN;
    int start = g_ib[rowBase + node];
    int end   = g_ib[curBase + node];
    const float* inB = (inExt ? ext : (g_buf + inOff)) + sub * 4;
    const int2* evp = g_ev + evBase;
    float ax = 0.f, ay = 0.f, az = 0.f, aw = 0.f;
    for (int e = start; e < end; e++) {
        int2  ev = evp[e];
        float w  = __int_as_float(ev.y);
        const float4 v = __ldg((const float4*)(inB + (size_t)ev.x * inLd));
        ax = fmaf(w, v.x, ax);
        ay = fmaf(w, v.y, ay);
        az = fmaf(w, v.z, az);
        aw = fmaf(w, v.w, aw);
    }
    float4 r;
    if (hasPrev) {
        const float4* pp = (const float4*)((prevExt ? ext : (g_buf + prevOff))
                                           + (size_t)node * prevLd + sub * 4);
        const float4 p = prevStream ? __ldcs(pp) : *pp;
        r.x = 2.f * ax - p.x; r.y = 2.f * ay - p.y;
        r.z = 2.f * az - p.z; r.w = 2.f * aw - p.w;
    } else {
        r.x = ax; r.y = ay; r.z = az; r.w = aw;
    }
    *(float4*)&g_buf[outOff + (size_t)node * LD + sub * 4] = r;
}

// ============================================================
// weight transpose + bf16x2 pack
// ============================================================
__global__ void k_transb(const float* __restrict__ W, int Kdim, int FOUT) {
    int K2 = Kdim / 2;
    int t = blockIdx.x * blockDim.x + threadIdx.x;
    if (t >= FOUT * K2) return;
    int n = t / K2, k2 = t % K2;
    float lo = W[(size_t)(2 * k2) * FOUT + n];
    float hi = W[(size_t)(2 * k2 + 1) * FOUT + n];
    g_buf[OFF_WT + t] = __uint_as_float(pack_bf16(lo, hi));
}

// ============================================================
// bf16 mma.sync GEMM: C[:, hc0 + n0 : +BN] = relu(A[NN,Kdim] @ WT^T + bias)
// A chunks with k0 < kSplit read the original slice-0 source (ext if x0Ext,
// else g_buf[x0Off], ld x0ld); the rest read TX (g_buf[aOff], ld lda).
// ============================================================
template<int BN, int BK>
__global__ void __launch_bounds__(256)
gemm_bf16(const float* __restrict__ ext, int x0Ext, size_t x0Off, int x0ld, int kSplit,
          size_t aOff, int lda, int Kdim,
          const float* __restrict__ bias, size_t cOff, int ldc, int hc0) {
    constexpr int BM = 128;
    constexpr int PW = BK / 2 + 4;
    constexpr int KS = BK / 16;
    constexpr int NT = BN / 32;
    constexpr int ASZ = BM * PW;
    constexpr int BSZ = BN * PW;
    constexpr int AOCT = BM * BK / 8;
    constexpr int AO_PER = (AOCT + 255) / 256;
    constexpr int BQ  = BN * BK / 8;
    constexpr int BO_PER = (BQ + 255) / 256;
    constexpr int OPR = BK / 8;

    __shared__ uint32_t sm[2 * ASZ + 2 * BSZ];
    uint32_t* As[2] = { sm, sm + ASZ };
    uint32_t* Bs[2] = { sm + 2 * ASZ, sm + 2 * ASZ + BSZ };

    int tid  = threadIdx.x;
    int wid  = tid >> 5;
    int lane = tid & 31;
    int wm   = wid >> 2;
    int wn   = wid & 3;
    int m0   = blockIdx.x * BM;
    int n0   = blockIdx.y * BN;
    int l4   = lane >> 2;
    int lq   = lane & 3;
    const int K2 = Kdim / 2;
    const uint32_t* WTu = (const uint32_t*)&g_buf[OFF_WT];
    const float* x0base = x0Ext ? ext : (g_buf + x0Off);

    float acc[4][NT][4];
    #pragma unroll
    for (int mt = 0; mt < 4; mt++)
        #pragma unroll
        for (int nt = 0; nt < NT; nt++)
            #pragma unroll
            for (int q = 0; q < 4; q++) acc[mt][nt][q] = 0.f;

    const int NC = Kdim / BK;

    float4 ra[AO_PER][2];
    uint4  rb[BO_PER];

    auto ldg = [&](int kc) {
        int k0 = kc * BK;
        const float* ap = (k0 < kSplit) ? x0base : (g_buf + aOff);
        int          al = (k0 < kSplit) ? x0ld   : lda;
        #pragma unroll
        for (int i = 0; i < AO_PER; i++) {
            int id = tid + i * 256;
            int r = id / OPR, o = id % OPR;
            int gr = m0 + r;
            if (gr < NN) {
                ra[i][0] = *(const float4*)&ap[(size_t)gr * al + k0 + o * 8];
                ra[i][1] = *(const float4*)&ap[(size_t)gr * al + k0 + o * 8 + 4];
            } else {
                ra[i][0] = make_float4(0.f, 0.f, 0.f, 0.f);
                ra[i][1] = make_float4(0.f, 0.f, 0.f, 0.f);
            }
        }
        #pragma unroll
        for (int i = 0; i < BO_PER; i++) {
            int id = tid + i * 256;
            if ((BQ & 255) == 0 || id < BQ) {
                int r = id / OPR, q = id % OPR;
                rb[i] = *(const uint4*)&WTu[(size_t)(n0 + r) * K2 + kc * (BK / 2) + q * 4];
            }
        }
    };

    auto sts = [&](int st) {
        #pragma unroll
        for (int i = 0; i < AO_PER; i++) {
            int id = tid + i * 256;
            int r = id / OPR, o = id % OPR;
            uint4 u;
            u.x = pack_bf16(ra[i][0].x, ra[i][0].y);
            u.y = pack_bf16(ra[i][0].z, ra[i][0].w);
            u.z = pack_bf16(ra[i][1].x, ra[i][1].y);
            u.w = pack_bf16(ra[i][1].z, ra[i][1].w);
            *(uint4*)&As[st][r * PW + o * 4] = u;
        }
        #pragma unroll
        for (int i = 0; i < BO_PER; i++) {
            int id = tid + i * 256;
            if ((BQ & 255) == 0 || id < BQ) {
                int r = id / OPR, q = id % OPR;
                *(uint4*)&Bs[st][r * PW + q * 4] = rb[i];
            }
        }
    };

    auto compute = [&](int st) {
        const uint32_t* aB = As[st] + (wm * 64 + l4) * PW + lq;
        const uint32_t* bB = Bs[st] + (wn * (BN / 4) + l4) * PW + lq;
        #pragma unroll
        for (int ks = 0; ks < KS; ks++) {
            uint32_t af[4][4];
            #pragma unroll
            for (int mt = 0; mt < 4; mt++) {
                const uint32_t* p = aB + mt * 16 * PW + ks * 8;
                af[mt][0] = p[0];
                af[mt][1] = p[8 * PW];
                af[mt][2] = p[4];
                af[mt][3] = p[8 * PW + 4];
            }
            uint32_t bf[NT][2];
            #pragma unroll
            for (int nt = 0; nt < NT; nt++) {
                const uint32_t* q = bB + nt * 8 * PW + ks * 8;
                bf[nt][0] = q[0];
                bf[nt][1] = q[4];
            }
            #pragma unroll
            for (int mt = 0; mt < 4; mt++)
                #pragma unroll
                for (int nt = 0; nt < NT; nt++)
                    mma16816(acc[mt][nt], af[mt], bf[nt]);
        }
    };

    ldg(0);
    sts(0);
    __syncthreads();

    for (int c = 0; c < NC; c++) {
        int st = c & 1;
        bool has = (c + 1 < NC);
        if (has) ldg(c + 1);
        compute(st);
        if (has) sts(st ^ 1);
        __syncthreads();
    }

    #pragma unroll
    for (int mt = 0; mt < 4; mt++) {
        int row = m0 + wm * 64 + mt * 16 + l4;
        #pragma unroll
        for (int nt = 0; nt < NT; nt++) {
            int col = n0 + wn * (BN / 4) + nt * 8 + 2 * lq;
            float b0 = bias[col], b1 = bias[col + 1];
            if (row < NN) {
                float2 o0;
                o0.x = fmaxf(acc[mt][nt][0] + b0, 0.f);
                o0.y = fmaxf(acc[mt][nt][1] + b1, 0.f);
                *(float2*)&g_buf[cOff + (size_t)row * ldc + hc0 + col] = o0;
            }
            if (row + 8 < NN) {
                float2 o1;
                o1.x = fmaxf(acc[mt][nt][2] + b0, 0.f);
                o1.y = fmaxf(acc[mt][nt][3] + b1, 0.f);
                *(float2*)&g_buf[cOff + (size_t)(row + 8) * ldc + hc0 + col] = o1;
            }
        }
    }
}

// ============================================================
// pooling + head
// ============================================================
__global__ void k_cnt(const int* __restrict__ batch) {
    int i = blockIdx.x * blockDim.x + threadIdx.x;
    if (i >= NN) return;
    atomicAdd(&g_buf[OFF_CNT + batch[i]], 1.0f);
}

__global__ void pool_kernel(const int* __restrict__ batch) {
    constexpr int NPB = 512;
    __shared__ int sb[NPB];
    int n0  = blockIdx.x * NPB;
    int tid = threadIdx.x;
    int nmax = NN - n0; if (nmax > NPB) nmax = NPB;
    if (tid < nmax) sb[tid] = batch[n0 + tid];
    __syncthreads();
    int f = tid;
    float acc = 0.f;
    int cur = sb[0];
    for (int i = 0; i < nmax; i++) {
        int b = sb[i];
        if (b != cur) {
            atomicAdd(&g_buf[OFF_POOL + (size_t)cur * 512 + f], acc);
            acc = 0.f; cur = b;
        }
        acc += g_buf[OFF_H2 + (size_t)(n0 + i) * 512 + f];
    }
    atomicAdd(&g_buf[OFF_POOL + (size_t)cur * 512 + f], acc);
}

__global__ void head_kernel(const float* __restrict__ fcw, const float* __restrict__ fcb,
                            float* __restrict__ out) {
    int g = blockIdx.x;
    int tid = threadIdx.x;
    __shared__ float red[128][4];
    float acc[4] = {0.f, 0.f, 0.f, 0.f};
    for (int j = tid; j < 512; j += 128) {
        float p = g_buf[OFF_POOL + (size_t)g * 512 + j];
        #pragma unroll
        for (int c = 0; c < 4; c++) acc[c] = fmaf(p, fcw[j * 4 + c], acc[c]);
    }
    #pragma unroll
    for (int c = 0; c < 4; c++) red[tid][c] = acc[c];
    __syncthreads();
    for (int s = 64; s > 0; s >>= 1) {
        if (tid < s) {
            #pragma unroll
            for (int c = 0; c < 4; c++) red[tid][c] += red[tid + s][c];
        }
        __syncthreads();
    }
    if (tid == 0) {
        float ic = 1.0f / fmaxf(g_buf[OFF_CNT + g], 1.0f);
        float l[4];
        #pragma unroll
        for (int c = 0; c < 4; c++) l[c] = red[0][c] * ic + fcb[c];
        float m = fmaxf(fmaxf(l[0], l[1]), fmaxf(l[2], l[3]));
        float s = 0.f;
        #pragma unroll
        for (int c = 0; c < 4; c++) s += expf(l[c] - m);
        float ls = logf(s);
        #pragma unroll
        for (int c = 0; c < 4; c++) out[g * 4 + c] = l[c] - m - ls;
    }
}

// ============================================================
// host side
// ============================================================
static inline int cdiv_ll(long long a, int b) { return (int)((a + b - 1) / b); }

// layer-1 conv (F=16): R11-shape SpMM chain, slice-0 = x (no copy)
static void run_conv1(const float* x, int rowBase, int curBase, int evBase,
                      const float* Wstack, const float* bias, int hc0) {
    int g = cdiv_ll((long long)NN * 4, 256);   // 4 lanes per node
    // T1: gather from x (ld 16)
    spmm_f<16><<<g, 256>>>(x, 1, 0, 16, 0, 0, 0, 0, OFF_TX + 16, 0,
                           rowBase, curBase, evBase);
    // T2: in = T1 (TX), prev = x (live -> normal load)
    spmm_f<16><<<g, 256>>>(x, 0, OFF_TX + 16, 80, 1, 0, 16, 0, OFF_TX + 32, 1,
                           rowBase, curBase, evBase);
    // T3, T4: prev = dead TX slices -> __ldcs
    spmm_f<16><<<g, 256>>>(nullptr, 0, OFF_TX + 32, 80, 0, OFF_TX + 16, 80, 1,
                           OFF_TX + 48, 1, rowBase, curBase, evBase);
    spmm_f<16><<<g, 256>>>(nullptr, 0, OFF_TX + 48, 80, 0, OFF_TX + 32, 80, 1,
                           OFF_TX + 64, 1, rowBase, curBase, evBase);
    k_transb<<<cdiv_ll(64 * 40, 256), 256>>>(Wstack, 80, 64);
    dim3 grid((NN + 127) / 128, 1);
    gemm_bf16<64, 16><<<grid, 256>>>(x, 1, 0, 16, 16, OFF_TX, 80, 80,
                                     bias, OFF_H1, 128, hc0);
}

// layer-2 conv (F=128): R11-shape SpMM chain, slice-0 = H1 (no copy)
static void run_conv2(int rowBase, int curBase, int evBase,
                      const float* Wstack, const float* bias, int hc0) {
    int g = cdiv_ll((long long)NN * 32, 256);  // 32 lanes per node
    // T1: gather from H1 (ld 128, dense)
    spmm_f<128><<<g, 256>>>(nullptr, 0, OFF_H1, 128, 0, 0, 0, 0,
                            OFF_TX + 128, 0, rowBase, curBase, evBase);
    // T2: in = T1 (TX), prev = H1 (live -> normal load)
    spmm_f<128><<<g, 256>>>(nullptr, 0, OFF_TX + 128, 640, 0, OFF_H1, 128, 0,
                            OFF_TX + 256, 1, rowBase, curBase, evBase);
    // T3, T4: prev = dead TX slices -> __ldcs
    spmm_f<128><<<g, 256>>>(nullptr, 0, OFF_TX + 256, 640, 0, OFF_TX + 128, 640, 1,
                            OFF_TX + 384, 1, rowBase, curBase, evBase);
    spmm_f<128><<<g, 256>>>(nullptr, 0, OFF_TX + 384, 640, 0, OFF_TX + 256, 640, 1,
                            OFF_TX + 512, 1, rowBase, curBase, evBase);
    k_transb<<<cdiv_ll(256 * 320, 256), 256>>>(Wstack, 640, 256);
    dim3 grid((NN + 127) / 128, 2);
    gemm_bf16<128, 32><<<grid, 256>>>(nullptr, 0, OFF_H1, 128, 128, OFF_TX, 640, 640,
                                      bias, OFF_H2, 512, hc0);
}

extern "C" void kernel_launch(void* const* d_in, const int* in_sizes, int n_in,
                              void* d_out, int out_size) {
    const float* x     = (const float*)d_in[0];
    const int*   ei    = (const int*)d_in[1];
    const int*   batch = (const int*)d_in[2];
    const float* W11   = (const float*)d_in[3];
    const float* b11   = (const float*)d_in[4];
    const float* W12   = (const float*)d_in[5];
    const float* b12   = (const float*)d_in[6];
    const float* W21   = (const float*)d_in[7];
    const float* b21   = (const float*)d_in[8];
    const float* W22   = (const float*)d_in[9];
    const float* b22   = (const float*)d_in[10];
    const float* fcw   = (const float*)d_in[11];
    const float* fcb   = (const float*)d_in[12];
    float* out = (float*)d_out;

    const int* src = ei;
    const int* dst = ei + NE;

    k_zero<<<cdiv_ll(2 * NN, 256), 256>>>(OFF_DEGA, 2 * NN);
    k_zero<<<cdiv_ll(NG * 512 + NG, 256), 256>>>(OFF_POOL, NG * 512 + NG);

    k_deg<<<cdiv_ll(NE, 256), 256>>>(src, dst);
    k_dinv<<<cdiv_ll(NN, 256), 256>>>();

    k_blocksum<<<NB, 1024>>>();
    k_scanblocks<<<1, 128>>>();
    k_writerow<<<NB, 1024>>>();
    k_scatter<<<cdiv_ll(NE, 256), 256>>>(src, dst);

    // strictly serial chains (concurrency thrashes L2: R12/R13)
    run_conv1(x, IB_ROWF, IB_CURF, 0,  W11, b11, 0);
    run_conv1(x, IB_ROWR, IB_CURR, NE, W12, b12, 64);

    run_conv2(IB_ROWF, IB_CURF, 0,  W21, b21, 0);
    run_conv2(IB_ROWR, IB_CURR, NE, W22, b22, 256);

    k_cnt<<<cdiv_ll(NN, 256), 256>>>(batch);
    pool_kernel<<<(NN + 511) / 512, 512>>>(batch);
    head_kernel<<<NG, 128>>>(fcw, fcb, out);
}